// round 11
// baseline (speedup 1.0000x reference)
#include <cuda_runtime.h>
#include <math.h>

#define H        128
#define WST      132      // weight row stride (words); 132%32==4
#define VS       140      // vector sample stride (holds 128 + 4 pad)
#define VIX(s,j) ((s)*VS + (j) + ((((j)>>6))<<2))   // 4-word pad at j=64
#define NCTA     128
#define NTHREADS 512
#define MAXIT    500
#define TOLF     1e-3f

// per-(iteration, CTA) residual slots; -1 = not posted, >=0 = posted value.
__device__ float g_part[MAXIT * NCTA];

struct __align__(16) Smem {
    float Wy0[H * WST];
    float Wy1[H * WST];
    float W1p[H * WST];
    float xbuf[2 * VS];
    float ubuf0[2 * VS];
    float ubuf1[2 * VS];
    float yv0[2 * VS];
    float yv1[2 * VS];
    float zz [2 * VS];
    float v2 [2 * VS];
    float v1 [2 * VS];
    float red[16];
    float zu2[2];
    int   flag;
};

__global__ void pblnn_init_kernel() {
    int t = blockIdx.x * blockDim.x + threadIdx.x;
    if (t < MAXIT * NCTA) g_part[t] = -1.f;
}

__device__ __forceinline__ float softplus_f(float s) {
    float e = __expf(s);
    float z = __logf(1.f + e);
    return (s > 15.f) ? s : z;
}

// 64-wide single-sample row dot, gmem weights (one-time precompute).
__device__ __forceinline__ float pdot1(const float* __restrict__ Wrow,
                                       const float* vecs, int jo, int pad) {
    float a = 0.f, b = 0.f;
#pragma unroll
    for (int t = 0; t < 16; t += 2) {
        float4 w  = __ldg((const float4*)&Wrow[jo + 4*t]);
        float4 w2 = __ldg((const float4*)&Wrow[jo + 4*t + 4]);
        float4 x  = *(const float4*)&vecs[jo + pad + 4*t];
        float4 x2 = *(const float4*)&vecs[jo + pad + 4*t + 4];
        a += w.x*x.x + w.y*x.y + w.z*x.z + w.w*x.w;
        b += w2.x*x2.x + w2.y*x2.y + w2.z*x2.z + w2.w*x2.w;
    }
    return a + b;
}

// 64-wide single-sample row dot, smem weights (stride WST).
__device__ __forceinline__ float sdot1(const float* Wrow, const float* vecs,
                                       int jo, int pad) {
    float a = 0.f, b = 0.f;
#pragma unroll
    for (int t = 0; t < 16; t += 2) {
        float4 w  = *(const float4*)&Wrow[jo + 4*t];
        float4 w2 = *(const float4*)&Wrow[jo + 4*t + 4];
        float4 x  = *(const float4*)&vecs[jo + pad + 4*t];
        float4 x2 = *(const float4*)&vecs[jo + pad + 4*t + 4];
        a += w.x*x.x + w.y*x.y + w.z*x.z + w.w*x.w;
        b += w2.x*x2.x + w2.y*x2.y + w2.z*x2.z + w2.w*x2.w;
    }
    return a + b;
}

// 64-deep single-sample column dot over TWO matrices (shared vector loads).
__device__ __forceinline__ void cdot2m(const float* WA, const float* WB,
                                       const float* vecs, int h, int half,
                                       float& rA, float& rB) {
    float a = 0.f, b = 0.f;
    const int jo = half * 64, pad = half * 4;
#pragma unroll
    for (int t = 0; t < 16; t++) {
        int j = jo + ((4*t + 4*half) & 63);
        float4 x = *(const float4*)&vecs[j + pad];
        const float* cA = &WA[j * WST + h];
        a += cA[0]*x.x + cA[WST]*x.y + cA[2*WST]*x.z + cA[3*WST]*x.w;
        const float* cB = &WB[j * WST + h];
        b += cB[0]*x.x + cB[WST]*x.y + cB[2*WST]*x.z + cB[3*WST]*x.w;
    }
    rA = a; rB = b;
}

// 64-deep single-sample column dot, one matrix.
__device__ __forceinline__ float cdot1m(const float* Wm, const float* vecs,
                                        int h, int half) {
    float a = 0.f;
    const int jo = half * 64, pad = half * 4;
#pragma unroll
    for (int t = 0; t < 16; t++) {
        int j = jo + ((4*t + 4*half) & 63);
        float4 x = *(const float4*)&vecs[j + pad];
        const float* c = &Wm[j * WST + h];
        a += c[0]*x.x + c[WST]*x.y + c[2*WST]*x.z + c[3*WST]*x.w;
    }
    return a;
}

#define COMB(r)  { r += __shfl_xor_sync(0xffffffffu, r, 16); }
#define WRED16(r) { r += __shfl_xor_sync(0xffffffffu, r, 1); \
                    r += __shfl_xor_sync(0xffffffffu, r, 2); \
                    r += __shfl_xor_sync(0xffffffffu, r, 4); \
                    r += __shfl_xor_sync(0xffffffffu, r, 8); }

__global__ __launch_bounds__(NTHREADS, 1)
void pblnn_kernel(
    const float* __restrict__ x,      const float* __restrict__ y,
    const float* __restrict__ wuu0_w, const float* __restrict__ wuu0_b,
    const float* __restrict__ wyu0_w, const float* __restrict__ wyu0_b,
    const float* __restrict__ wy0,
    const float* __restrict__ wu0_w,  const float* __restrict__ wu0_b,
    const float* __restrict__ wuu1_w, const float* __restrict__ wuu1_b,
    const float* __restrict__ wzu1_w, const float* __restrict__ wzu1_b,
    const float* __restrict__ wz1,
    const float* __restrict__ wyu1_w, const float* __restrict__ wyu1_b,
    const float* __restrict__ wy1,
    const float* __restrict__ wu1_w,  const float* __restrict__ wu1_b,
    const float* __restrict__ wzu2_w, const float* __restrict__ wzu2_b,
    const float* __restrict__ wz2,
    const float* __restrict__ wyu2_w, const float* __restrict__ wyu2_b,
    const float* __restrict__ wy2,
    float* __restrict__ out)
{
    extern __shared__ char smem_raw[];
    Smem& S = *reinterpret_cast<Smem*>(smem_raw);

    const int tid  = threadIdx.x;
    const int l    = tid & 31;
    const int w    = tid >> 5;
    const int s    = w >> 3;            // warp-group = sample
    const int wg   = w & 7;
    const int hb   = l & 15;
    const int half = l >> 4;
    const int h    = wg * 16 + hb;
    const bool lead = (half == 0);
    const int jo   = half * 64;
    const int pad  = half * 4;
    const int samp = blockIdx.x * 2;

    // ---- stage weights (fp32, stride WST) + x (VIX layout) ----
    for (int e = tid; e < H * H / 4; e += NTHREADS) {
        int r = e >> 5, c4 = (e & 31) * 4;
        *(float4*)&S.Wy0[r * WST + c4] = __ldg((const float4*)&wy0[r * H + c4]);
        *(float4*)&S.Wy1[r * WST + c4] = __ldg((const float4*)&wy1[r * H + c4]);
        float4 wv = __ldg((const float4*)&wz1[r * H + c4]);
        wv.x = fmaxf(wv.x, 0.f); wv.y = fmaxf(wv.y, 0.f);
        wv.z = fmaxf(wv.z, 0.f); wv.w = fmaxf(wv.w, 0.f);
        *(float4*)&S.W1p[r * WST + c4] = wv;
    }
    for (int e = tid; e < 2 * H; e += NTHREADS) {
        int ss = e >> 7, j = e & 127;
        S.xbuf[VIX(ss, j)] = x[samp * H + e];
    }
    __syncthreads();

    const float* xb = &S.xbuf[s * VS];
    const float* u0b = &S.ubuf0[s * VS];
    const float* u1b = &S.ubuf1[s * VS];

    // ---- y-independent precompute: every thread serves its own sample ----
    float a0r = 0.f, c0r = 0.f, zur = 0.f, a1r = 0.f, c1r = 0.f;
    float a2w = 0.f, vw2 = 0.f, yr = 0.f;
    float y1r = 1.f, yh = 1.f, zs1r = 0.f, gAr = 0.f, my1r = 0.f;

    // R1: u0 = sp(wuu0@x+b) -> smem ; a0 = wyu0@x+b -> reg
    {
        float p = pdot1(&wuu0_w[h * H], xb, jo, pad);
        float qv = pdot1(&wyu0_w[h * H], xb, jo, pad);
        COMB(p) COMB(qv)
        if (lead) {
            S.ubuf0[VIX(s, h)] = softplus_f(p + wuu0_b[h]);
            a0r = qv + wyu0_b[h];
        }
    }
    __syncthreads();
    // R2: c0 = wu0@x+b -> reg ; u1 = sp(wuu1@u0+b) -> smem
    {
        float p = pdot1(&wu0_w[h * H], xb, jo, pad);
        float qv = pdot1(&wuu1_w[h * H], u0b, jo, pad);
        COMB(p) COMB(qv)
        if (lead) {
            c0r = p + wu0_b[h];
            S.ubuf1[VIX(s, h)] = softplus_f(qv + wuu1_b[h]);
        }
    }
    __syncthreads();
    // R3+R4: zur, a1, c1 (from u0) ; a2t (from u1) ; zu2 (warp 0/8)
    {
        float p = pdot1(&wzu1_w[h * H], u0b, jo, pad);
        float qv = pdot1(&wyu1_w[h * H], u0b, jo, pad);
        float rv = pdot1(&wu1_w[h * H], u0b, jo, pad);
        float tv = pdot1(&wyu2_w[h * H], u1b, jo, pad);
        COMB(p) COMB(qv) COMB(rv) COMB(tv)
        if (lead) {
            zur = softplus_f(p + wzu1_b[h]);
            a1r = qv + wyu1_b[h];
            c1r = rv + wu1_b[h];
            a2w = (tv + wyu2_b[h]) * wy2[h];
        }
        if (wg == 0) {   // warps 0 and 8: zu2[s]
            float4 wv = __ldg((const float4*)&wzu2_w[4 * l]);
            int j4 = 4 * l, pd = (j4 >> 6) << 2;
            float4 uv = *(const float4*)&u1b[j4 + pd];
            float sv = wv.x*uv.x + wv.y*uv.y + wv.z*uv.z + wv.w*uv.w;
#pragma unroll
            for (int o = 16; o; o >>= 1)
                sv += __shfl_xor_sync(0xffffffffu, sv, o);
            if (l == 0) S.zu2[s] = softplus_f(sv + wzu2_b[0]);
        }
    }
    __syncthreads();
    if (lead) {
        vw2 = S.zu2[s] * fmaxf(wz2[h], 0.f);
        yr = y[(samp + s) * H + h];
        S.yv0[VIX(s, h)] = a0r;   // y1 = 1
        S.yv1[VIX(s, h)] = a1r;
    }
    __syncthreads();   // yv ready for iter 0

    const float* yv0b = &S.yv0[s * VS];
    const float* yv1b = &S.yv1[s * VS];
    const float* zzb  = &S.zz[s * VS];
    const float* v2b  = &S.v2[s * VS];
    const float* v1b  = &S.v1[s * VS];

    // ---- fixed-point iterations: 4 barriers/iter, lag-2 pipeline ----
    int broke = 0;
    for (int it = 0; it < MAXIT; ++it) {
        // poster (w8,l0) + checker (w12) overlap with P1
        if (w == 8 && l == 0 && it > 0) {
            float n0 = 0.f, n1 = 0.f;
#pragma unroll
            for (int i = 0; i < 8; i++) { n0 += S.red[i]; n1 += S.red[i + 8]; }
            *((volatile float*)&g_part[(it - 1) * NCTA + blockIdx.x])
                = sqrtf(n0) + sqrtf(n1);
        }
        if (w == 12) {
            int f = 0;
            if (it >= 2) {
                volatile const float* gp = &g_part[(it - 2) * NCTA];
                float sum;
                for (;;) {
                    float v0 = gp[l], v1v = gp[l + 32];
                    float v2v = gp[l + 64], v3 = gp[l + 96];
                    bool ok = (v0 >= 0.f) & (v1v >= 0.f) & (v2v >= 0.f) & (v3 >= 0.f);
                    if (__all_sync(0xffffffffu, ok)) { sum = v0 + v1v + v2v + v3; break; }
                }
#pragma unroll
                for (int o = 16; o; o >>= 1)
                    sum += __shfl_xor_sync(0xffffffffu, sum, o);
                if (sum * (1.f / 256.f) < TOLF) f = 1;
            }
            if (l == 0) S.flag = f;
        }

        // P1: m1 = Wy0@yv0 ; my1 = Wy1@yv1 (own sample)
        {
            float m1 = sdot1(&S.Wy0[h * WST], yv0b, jo, pad);
            float m2 = sdot1(&S.Wy1[h * WST], yv1b, jo, pad);
            COMB(m1) COMB(m2)
            if (lead) {
                float s1 = m1 + c0r;
                float e = __expf(s1);
                float z1 = __logf(1.f + e);
                float sg1 = e / (1.f + e);
                if (s1 > 15.f) { z1 = s1; sg1 = 1.f; }
                zs1r = sg1 * zur;
                my1r = m2;
                S.zz[VIX(s, h)] = z1 * zur;
            }
        }
        __syncthreads();                                   // bar 1

        // P2: s2 = W1p@zz + my1 + c1 -> v2
        {
            float mA = sdot1(&S.W1p[h * WST], zzb, jo, pad);
            COMB(mA)
            if (lead) {
                float s2 = mA + my1r + c1r;
                S.v2[VIX(s, h)] = vw2 / (1.f + __expf(-s2));
            }
        }
        __syncthreads();                                   // bar 2

        // P3: tv = W1p^T@v2 -> v1 ; gA = Wy1^T@v2 -> reg
        {
            float tv, gA;
            cdot2m(S.W1p, S.Wy1, v2b, h, half, tv, gA);
            COMB(tv) COMB(gA)
            if (lead) {
                gAr = gA;
                S.v1[VIX(s, h)] = tv * zs1r;
            }
        }
        __syncthreads();                                   // bar 3

        // flag = conv(it-2): break before this iteration's update; revert below.
        if (S.flag) { broke = 1; break; }

        // P4: gB = Wy0^T@v1 -> g, rres, update, residual reduce
        {
            float gB = cdot1m(S.Wy0, v1b, h, half);
            COMB(gB)
            float qq = 0.f;
            if (lead) {
                float g = a1r * gAr + a0r * gB + a2w + 0.5f * y1r;
                float rres = yr - g;
                qq = rres * rres;
                yh = y1r;                          // y1_after(it-1)
                y1r += (4.f / (float)(it + 1)) * rres;
                S.yv0[VIX(s, h)] = y1r * a0r;
                S.yv1[VIX(s, h)] = y1r * a1r;
            }
            WRED16(qq)
            if (l == 0) S.red[w] = qq;
        }
        __syncthreads();                                   // bar 4
    }
    if (broke) y1r = yh;   // exact revert to y1_after(break_it - 2)

    // ---- output: mean over dims of (y1 + y) per sample ----
    {
        float o = lead ? (y1r + yr) : 0.f;
        WRED16(o)
        if (l == 0) S.red[w] = o;
    }
    __syncthreads();
    if (tid == 0) {
        float t0 = 0.f, t1 = 0.f;
#pragma unroll
        for (int i = 0; i < 8; i++) { t0 += S.red[i]; t1 += S.red[i + 8]; }
        out[samp]     = t0 * (1.f / 128.f);
        out[samp + 1] = t1 * (1.f / 128.f);
    }
}

extern "C" void kernel_launch(void* const* d_in, const int* in_sizes, int n_in,
                              void* d_out, int out_size) {
    (void)in_sizes; (void)n_in; (void)out_size;
    const float* x      = (const float*)d_in[0];
    const float* y      = (const float*)d_in[1];
    const float* wuu0_w = (const float*)d_in[2];
    const float* wuu0_b = (const float*)d_in[3];
    const float* wyu0_w = (const float*)d_in[4];
    const float* wyu0_b = (const float*)d_in[5];
    const float* wy0    = (const float*)d_in[6];
    const float* wu0_w  = (const float*)d_in[7];
    const float* wu0_b  = (const float*)d_in[8];
    const float* wuu1_w = (const float*)d_in[9];
    const float* wuu1_b = (const float*)d_in[10];
    const float* wzu1_w = (const float*)d_in[11];
    const float* wzu1_b = (const float*)d_in[12];
    const float* wz1    = (const float*)d_in[13];
    const float* wyu1_w = (const float*)d_in[14];
    const float* wyu1_b = (const float*)d_in[15];
    const float* wy1    = (const float*)d_in[16];
    const float* wu1_w  = (const float*)d_in[17];
    const float* wu1_b  = (const float*)d_in[18];
    const float* wzu2_w = (const float*)d_in[19];
    const float* wzu2_b = (const float*)d_in[20];
    const float* wz2    = (const float*)d_in[21];
    const float* wyu2_w = (const float*)d_in[22];
    const float* wyu2_b = (const float*)d_in[23];
    const float* wy2    = (const float*)d_in[24];
    // d_in[25] (wu2_w), d_in[26] (wu2_b) do not affect the gradient / output.

    size_t smem = sizeof(Smem);
    cudaFuncSetAttribute(pblnn_kernel, cudaFuncAttributeMaxDynamicSharedMemorySize, (int)smem);

    pblnn_init_kernel<<<(MAXIT * NCTA + 255) / 256, 256>>>();
    pblnn_kernel<<<NCTA, NTHREADS, smem>>>(
        x, y,
        wuu0_w, wuu0_b, wyu0_w, wyu0_b, wy0, wu0_w, wu0_b,
        wuu1_w, wuu1_b, wzu1_w, wzu1_b, wz1, wyu1_w, wyu1_b, wy1, wu1_w, wu1_b,
        wzu2_w, wzu2_b, wz2, wyu2_w, wyu2_b, wy2,
        (float*)d_out);
}

// round 12
// speedup vs baseline: 1.7309x; 1.7309x over previous
#include <cuda_runtime.h>
#include <math.h>

#define H        128
#define B        256
#define WST      132      // fp32 stride: 132 % 32 == 4 -> conflict-free row+col access
#define SP       260      // packed float2 matrix stride (260 % 32 == 4)
#define PW       (2 * H + 8)
#define NCTA     128
#define NTHREADS 512
#define MAXIT    500
#define TOLF     1e-3f
#define PCTA     64       // precompute CTAs
#define PS       4        // samples per precompute CTA

// per-(iteration, CTA) residual slots; -1 = not posted, >=0 = posted value.
__device__ float g_part[65536];          // >= MAXIT*NCTA, padded for unguarded init
// per-sample loop constants: [a0, c0, zur, a1, c1, a2w, vw2]
__device__ float g_c[7][B * H];

// ============================ precompute kernel ============================

struct __align__(16) PSmem {
    float xb[PS][WST];
    float u0[PS][WST];
    float u1[PS][WST];
    float PB[4][4][PS][WST];    // [buf][q][sample][h]
    float zu2[PS];
};

// one gmem weight row segment (32 wide) dotted against 4 smem sample vectors
__device__ __forceinline__ void qd4(const float* __restrict__ wseg,
                                    const float V[PS][WST], int k0,
                                    float& p0, float& p1, float& p2, float& p3) {
    p0 = p1 = p2 = p3 = 0.f;
#pragma unroll
    for (int c = 0; c < 8; c++) {
        float4 w = __ldg((const float4*)&wseg[4 * c]);
        float4 a = *(const float4*)&V[0][k0 + 4 * c];
        float4 b = *(const float4*)&V[1][k0 + 4 * c];
        float4 d = *(const float4*)&V[2][k0 + 4 * c];
        float4 e = *(const float4*)&V[3][k0 + 4 * c];
        p0 += w.x*a.x + w.y*a.y + w.z*a.z + w.w*a.w;
        p1 += w.x*b.x + w.y*b.y + w.z*b.z + w.w*b.w;
        p2 += w.x*d.x + w.y*d.y + w.z*d.z + w.w*d.w;
        p3 += w.x*e.x + w.y*e.y + w.z*e.z + w.w*e.w;
    }
}

__device__ __forceinline__ float softplus_f(float s) {
    float e = __expf(s);
    float z = __logf(1.f + e);
    return (s > 15.f) ? s : z;
}

__global__ __launch_bounds__(512, 1)
void pblnn_pre_kernel(
    const float* __restrict__ x,
    const float* __restrict__ wuu0_w, const float* __restrict__ wuu0_b,
    const float* __restrict__ wyu0_w, const float* __restrict__ wyu0_b,
    const float* __restrict__ wu0_w,  const float* __restrict__ wu0_b,
    const float* __restrict__ wuu1_w, const float* __restrict__ wuu1_b,
    const float* __restrict__ wzu1_w, const float* __restrict__ wzu1_b,
    const float* __restrict__ wyu1_w, const float* __restrict__ wyu1_b,
    const float* __restrict__ wu1_w,  const float* __restrict__ wu1_b,
    const float* __restrict__ wzu2_w, const float* __restrict__ wzu2_b,
    const float* __restrict__ wz2,
    const float* __restrict__ wyu2_w, const float* __restrict__ wyu2_b,
    const float* __restrict__ wy2)
{
    __shared__ PSmem P;
    const int tid = threadIdx.x;
    const int h   = tid & 127;
    const int q   = tid >> 7;
    const int k0  = q * 32;
    const int l   = tid & 31;
    const int w   = tid >> 5;
    const int samp0 = blockIdx.x * PS;

    // reset residual slots (replaces init kernel): 64*512*2 = 65536 slots
    {
        int t = blockIdx.x * 512 + tid;
        g_part[t] = -1.f;
        g_part[t + 32768] = -1.f;
    }

    for (int e = tid; e < PS * H; e += 512)
        P.xb[e >> 7][e & 127] = x[samp0 * H + e];
    __syncthreads();

    // Round A: {wuu0, wyu0, wu0} @ x
    {
        float p0, p1, p2, p3;
        qd4(&wuu0_w[h * H + k0], P.xb, k0, p0, p1, p2, p3);
        P.PB[0][q][0][h] = p0; P.PB[0][q][1][h] = p1;
        P.PB[0][q][2][h] = p2; P.PB[0][q][3][h] = p3;
        qd4(&wyu0_w[h * H + k0], P.xb, k0, p0, p1, p2, p3);
        P.PB[1][q][0][h] = p0; P.PB[1][q][1][h] = p1;
        P.PB[1][q][2][h] = p2; P.PB[1][q][3][h] = p3;
        qd4(&wu0_w[h * H + k0], P.xb, k0, p0, p1, p2, p3);
        P.PB[2][q][0][h] = p0; P.PB[2][q][1][h] = p1;
        P.PB[2][q][2][h] = p2; P.PB[2][q][3][h] = p3;
    }
    __syncthreads();
    // combine: thread (h,q) handles sample q
    {
        int gi = (samp0 + q) * H + h;
        float t0 = P.PB[0][0][q][h] + P.PB[0][1][q][h] + P.PB[0][2][q][h] + P.PB[0][3][q][h];
        P.u0[q][h] = softplus_f(t0 + wuu0_b[h]);
        g_c[0][gi] = P.PB[1][0][q][h] + P.PB[1][1][q][h] + P.PB[1][2][q][h] + P.PB[1][3][q][h] + wyu0_b[h];
        g_c[1][gi] = P.PB[2][0][q][h] + P.PB[2][1][q][h] + P.PB[2][2][q][h] + P.PB[2][3][q][h] + wu0_b[h];
    }
    __syncthreads();

    // Round B: {wuu1, wzu1, wyu1, wu1} @ u0
    {
        float p0, p1, p2, p3;
        qd4(&wuu1_w[h * H + k0], P.u0, k0, p0, p1, p2, p3);
        P.PB[0][q][0][h] = p0; P.PB[0][q][1][h] = p1;
        P.PB[0][q][2][h] = p2; P.PB[0][q][3][h] = p3;
        qd4(&wzu1_w[h * H + k0], P.u0, k0, p0, p1, p2, p3);
        P.PB[1][q][0][h] = p0; P.PB[1][q][1][h] = p1;
        P.PB[1][q][2][h] = p2; P.PB[1][q][3][h] = p3;
        qd4(&wyu1_w[h * H + k0], P.u0, k0, p0, p1, p2, p3);
        P.PB[2][q][0][h] = p0; P.PB[2][q][1][h] = p1;
        P.PB[2][q][2][h] = p2; P.PB[2][q][3][h] = p3;
        qd4(&wu1_w[h * H + k0], P.u0, k0, p0, p1, p2, p3);
        P.PB[3][q][0][h] = p0; P.PB[3][q][1][h] = p1;
        P.PB[3][q][2][h] = p2; P.PB[3][q][3][h] = p3;
    }
    __syncthreads();
    {
        int gi = (samp0 + q) * H + h;
        float t0 = P.PB[0][0][q][h] + P.PB[0][1][q][h] + P.PB[0][2][q][h] + P.PB[0][3][q][h];
        P.u1[q][h] = softplus_f(t0 + wuu1_b[h]);
        float t1 = P.PB[1][0][q][h] + P.PB[1][1][q][h] + P.PB[1][2][q][h] + P.PB[1][3][q][h];
        g_c[2][gi] = softplus_f(t1 + wzu1_b[h]);
        g_c[3][gi] = P.PB[2][0][q][h] + P.PB[2][1][q][h] + P.PB[2][2][q][h] + P.PB[2][3][q][h] + wyu1_b[h];
        g_c[4][gi] = P.PB[3][0][q][h] + P.PB[3][1][q][h] + P.PB[3][2][q][h] + P.PB[3][3][q][h] + wu1_b[h];
    }
    __syncthreads();

    // Round C: wyu2 @ u1 ; zu2[s] by warps 0..PS-1
    {
        float p0, p1, p2, p3;
        qd4(&wyu2_w[h * H + k0], P.u1, k0, p0, p1, p2, p3);
        P.PB[0][q][0][h] = p0; P.PB[0][q][1][h] = p1;
        P.PB[0][q][2][h] = p2; P.PB[0][q][3][h] = p3;
    }
    if (w < PS) {
        float4 wv = __ldg((const float4*)&wzu2_w[4 * l]);
        float4 uv = *(const float4*)&P.u1[w][4 * l];
        float sv = wv.x*uv.x + wv.y*uv.y + wv.z*uv.z + wv.w*uv.w;
#pragma unroll
        for (int o = 16; o; o >>= 1)
            sv += __shfl_xor_sync(0xffffffffu, sv, o);
        if (l == 0) P.zu2[w] = softplus_f(sv + wzu2_b[0]);
    }
    __syncthreads();
    {
        int gi = (samp0 + q) * H + h;
        float t0 = P.PB[0][0][q][h] + P.PB[0][1][q][h] + P.PB[0][2][q][h] + P.PB[0][3][q][h];
        g_c[5][gi] = (t0 + wyu2_b[h]) * wy2[h];
        g_c[6][gi] = P.zu2[q] * fmaxf(wz2[h], 0.f);
    }
}

// ============================== main kernel ===============================

struct __align__(16) Smem {
    float Wy0[H * WST];       // fp32 rows (M1) + scalar cols (D)
    float WP[H * SP];         // interleaved (W1p, Wy1): rows (M2) + col float2 (C)
    float yv0[2][H];
    float yv1[2][H];
    float zz [2][H];
    float v2 [2][H];
    float v1 [2][H];
    float P1[4][PW];          // packed partials: [q][2h+s]
    float P2[4][PW];
    float red[8];
    int   flag;
};

__device__ __forceinline__ void spsig(float s, float& z, float& sg) {
    float e = __expf(s);
    float zz_ = __logf(1.f + e);
    float sgg = e / (1.f + e);
    if (s > 15.f) { zz_ = s; sgg = 1.f; }
    z = zz_; sg = sgg;
}

__global__ __launch_bounds__(NTHREADS, 1)
void pblnn_kernel(
    const float* __restrict__ y,
    const float* __restrict__ wy0,
    const float* __restrict__ wz1,
    const float* __restrict__ wy1,
    float* __restrict__ out)
{
    extern __shared__ char smem_raw[];
    Smem& S = *reinterpret_cast<Smem*>(smem_raw);

    const int tid  = threadIdx.x;
    const int lane = tid & 31;
    const int wrp  = tid >> 5;
    const int h    = tid & (H - 1);
    const int q    = tid >> 7;          // quarter 0..3
    const int k0   = q * 32;
    const bool act = (q < 2);           // elementwise lanes; s = q
    const int s    = q & 1;
    const int samp = blockIdx.x * 2;

    // ---- stage loop weights into smem ----
    for (int e = tid; e < H * H / 4; e += NTHREADS) {
        int r = e >> 5, c4 = (e & 31) * 4;
        *(float4*)&S.Wy0[r * WST + c4] = __ldg((const float4*)&wy0[r * H + c4]);
        float4 w1 = __ldg((const float4*)&wz1[r * H + c4]);
        w1.x = fmaxf(w1.x, 0.f); w1.y = fmaxf(w1.y, 0.f);
        w1.z = fmaxf(w1.z, 0.f); w1.w = fmaxf(w1.w, 0.f);
        float4 wy = __ldg((const float4*)&wy1[r * H + c4]);
        float4 lo = make_float4(w1.x, wy.x, w1.y, wy.y);
        float4 hi = make_float4(w1.z, wy.z, w1.w, wy.w);
        *(float4*)&S.WP[r * SP + 2 * c4]     = lo;
        *(float4*)&S.WP[r * SP + 2 * c4 + 4] = hi;
    }

    // ---- load per-sample constants from precompute scratch ----
    float a0r = 0.f, c0r = 0.f, zur = 0.f, a1r = 0.f, c1r = 0.f;
    float a2w = 0.f, vw2 = 0.f, yr = 0.f;
    float y1r = 1.f, yhist = 1.f, zs1r = 0.f, gAr = 0.f;
    if (act) {
        int gi = (samp + s) * H + h;
        a0r = g_c[0][gi];  c0r = g_c[1][gi];  zur = g_c[2][gi];
        a1r = g_c[3][gi];  c1r = g_c[4][gi];
        a2w = g_c[5][gi];  vw2 = g_c[6][gi];
        yr  = y[gi];
        S.yv0[s][h] = a0r;      // y1 = 1
        S.yv1[s][h] = a1r;
    }
    __syncthreads();            // weights + yv ready for iter 0

    // ---- fixed-point iterations: lag-2, atomic-free convergence pipeline ----
    int broke = 0;
    for (int it = 0; it < MAXIT; ++it) {
        // post residual of it-1: one plain volatile store, value doubles as flag
        if (tid == 416 && it > 0) {
            float n0 = sqrtf(S.red[0] + S.red[1] + S.red[2] + S.red[3]);
            float n1 = sqrtf(S.red[4] + S.red[5] + S.red[6] + S.red[7]);
            *((volatile float*)&g_part[(it - 1) * NCTA + blockIdx.x]) = n0 + n1;
        }
        // checker warp: cooperative poll + sum of lag-2 slots (overlaps M1)
        if (wrp == 12) {
            int f = 0;
            if (it >= 2) {
                volatile const float* gp = &g_part[(it - 2) * NCTA];
                float sum;
                for (;;) {
                    float v0 = gp[lane], v1 = gp[lane + 32];
                    float v2 = gp[lane + 64], v3 = gp[lane + 96];
                    bool ok = (v0 >= 0.f) & (v1 >= 0.f) & (v2 >= 0.f) & (v3 >= 0.f);
                    if (__all_sync(0xffffffffu, ok)) { sum = v0 + v1 + v2 + v3; break; }
                }
#pragma unroll
                for (int o = 16; o; o >>= 1)
                    sum += __shfl_xor_sync(0xffffffffu, sum, o);
                if (sum * (1.f / 256.f) < TOLF) f = 1;
            }
            if (lane == 0) S.flag = f;
        }

        // M1: s1 partial = Wy0[h][k0..k0+32) . yv0
        {
            const float4* W  = (const float4*)&S.Wy0[h * WST + k0];
            const float4* V0 = (const float4*)&S.yv0[0][k0];
            const float4* V1 = (const float4*)&S.yv0[1][k0];
            float m0a = 0.f, m0b = 0.f, m1a = 0.f, m1b = 0.f;
#pragma unroll
            for (int c = 0; c < 8; c += 2) {
                float4 w = W[c], a = V0[c], b = V1[c];
                m0a += w.x * a.x + w.y * a.y + w.z * a.z + w.w * a.w;
                m1a += w.x * b.x + w.y * b.y + w.z * b.z + w.w * b.w;
                float4 w2 = W[c + 1], a2 = V0[c + 1], b2 = V1[c + 1];
                m0b += w2.x * a2.x + w2.y * a2.y + w2.z * a2.z + w2.w * a2.w;
                m1b += w2.x * b2.x + w2.y * b2.y + w2.z * b2.z + w2.w * b2.w;
            }
            *(float2*)&S.P1[q][2 * h] = make_float2(m0a + m0b, m1a + m1b);
        }
        __syncthreads();                                   // #2

        // flag = conv(it-2), stable after #2; break BEFORE this iteration's update.
        // y1 currently = y1_after(it-1); required = y1_after(it-2) = yhist.
        if (S.flag) { broke = 1; break; }

        if (act) {
            int ix = 2 * h + s;
            float s1 = S.P1[0][ix] + S.P1[1][ix] + S.P1[2][ix] + S.P1[3][ix] + c0r;
            float z1, sg1;
            spsig(s1, z1, sg1);
            zs1r = sg1 * zur;
            S.zz[s][h] = z1 * zur;
        }
        __syncthreads();                                   // #3

        // M2: s2 partial = W1p@zz + Wy1@yv1 via packed WP rows
        {
            const float4* WA = (const float4*)&S.WP[h * SP + 2 * k0];
            const float4* Z0 = (const float4*)&S.zz[0][k0];
            const float4* Z1 = (const float4*)&S.zz[1][k0];
            const float4* Y0 = (const float4*)&S.yv1[0][k0];
            const float4* Y1 = (const float4*)&S.yv1[1][k0];
            float mA0 = 0.f, mA1 = 0.f, mB0 = 0.f, mB1 = 0.f;
#pragma unroll
            for (int c = 0; c < 8; c++) {
                float4 wlo = WA[2 * c];
                float4 whi = WA[2 * c + 1];
                float4 z0 = Z0[c], z1v = Z1[c], u0v = Y0[c], u1v = Y1[c];
                mA0 += wlo.x * z0.x + wlo.z * z0.y + whi.x * z0.z + whi.z * z0.w;
                mB0 += wlo.y * u0v.x + wlo.w * u0v.y + whi.y * u0v.z + whi.w * u0v.w;
                mA1 += wlo.x * z1v.x + wlo.z * z1v.y + whi.x * z1v.z + whi.z * z1v.w;
                mB1 += wlo.y * u1v.x + wlo.w * u1v.y + whi.y * u1v.z + whi.w * u1v.w;
            }
            *(float2*)&S.P1[q][2 * h] = make_float2(mA0 + mB0, mA1 + mB1);
        }
        __syncthreads();                                   // #4

        if (act) {
            int ix = 2 * h + s;
            float s2 = S.P1[0][ix] + S.P1[1][ix] + S.P1[2][ix] + S.P1[3][ix] + c1r;
            float sg2 = 1.f / (1.f + __expf(-s2));
            S.v2[s][h] = vw2 * sg2;
        }
        __syncthreads();                                   // #5

        // C: tv partial (W1p cols) + gA partial (Wy1 cols) via packed WP col float2
        {
            float tA0 = 0.f, tA1 = 0.f, gA0 = 0.f, gA1 = 0.f;
#pragma unroll
            for (int c = 0; c < 8; c++) {
                int kp = k0 + 4 * c;
                float4 a = *(const float4*)&S.v2[0][kp];
                float4 b = *(const float4*)&S.v2[1][kp];
#define STC(r, av, bv) { \
                float2 wc = *(const float2*)&S.WP[(kp + r) * SP + 2 * h]; \
                tA0 += (av) * wc.x;  tA1 += (bv) * wc.x; \
                gA0 += (av) * wc.y;  gA1 += (bv) * wc.y; }
                STC(0, a.x, b.x) STC(1, a.y, b.y) STC(2, a.z, b.z) STC(3, a.w, b.w)
#undef STC
            }
            *(float2*)&S.P1[q][2 * h] = make_float2(tA0, tA1);
            *(float2*)&S.P2[q][2 * h] = make_float2(gA0, gA1);
        }
        __syncthreads();                                   // #6

        if (act) {
            int ix = 2 * h + s;
            float tv = S.P1[0][ix] + S.P1[1][ix] + S.P1[2][ix] + S.P1[3][ix];
            gAr      = S.P2[0][ix] + S.P2[1][ix] + S.P2[2][ix] + S.P2[3][ix];
            S.v1[s][h] = tv * zs1r;
        }
        __syncthreads();                                   // #7

        // D: gB partial (Wy0 cols, scalar)
        {
            float g0 = 0.f, g1 = 0.f;
#pragma unroll
            for (int c = 0; c < 8; c++) {
                int kp = k0 + 4 * c;
                float4 a = *(const float4*)&S.v1[0][kp];
                float4 b = *(const float4*)&S.v1[1][kp];
#define STD(r, av, bv) { \
                float w = S.Wy0[(kp + r) * WST + h]; \
                g0 += (av) * w;  g1 += (bv) * w; }
                STD(0, a.x, b.x) STD(1, a.y, b.y) STD(2, a.z, b.z) STD(3, a.w, b.w)
#undef STD
            }
            *(float2*)&S.P1[q][2 * h] = make_float2(g0, g1);
        }
        __syncthreads();                                   // #8

        float rres = 0.f;
        if (act) {
            int ix = 2 * h + s;
            float gB = S.P1[0][ix] + S.P1[1][ix] + S.P1[2][ix] + S.P1[3][ix];
            float g = a1r * gAr + a0r * gB + a2w + 0.5f * y1r;
            rres = yr - g;
            float qq = rres * rres;
#pragma unroll
            for (int o = 16; o; o >>= 1)
                qq += __shfl_xor_sync(0xffffffffu, qq, o);
            if ((h & 31) == 0) S.red[tid >> 5] = qq;   // warps 0..7
        }

        if (act) {
            yhist = y1r;                       // y1_after(it-1)
            y1r += (4.f / (float)(it + 1)) * rres;
            S.yv0[s][h] = y1r * a0r;
            S.yv1[s][h] = y1r * a1r;
        }
        __syncthreads();     // #E: red/yv ready; flag not yet overwritten
    }
    if (broke && act) y1r = yhist;   // exact revert to y1_after(break_it - 2)

    // ---- output: mean over dims of (y1 + y) per sample ----
    float o = act ? (y1r + yr) : 0.f;
    if (act) {
#pragma unroll
        for (int off = 16; off; off >>= 1)
            o += __shfl_xor_sync(0xffffffffu, o, off);
        if ((h & 31) == 0) S.red[tid >> 5] = o;
    }
    __syncthreads();
    if (tid == 0) {
        out[samp]     = (S.red[0] + S.red[1] + S.red[2] + S.red[3]) * (1.f / 128.f);
        out[samp + 1] = (S.red[4] + S.red[5] + S.red[6] + S.red[7]) * (1.f / 128.f);
    }
}

extern "C" void kernel_launch(void* const* d_in, const int* in_sizes, int n_in,
                              void* d_out, int out_size) {
    (void)in_sizes; (void)n_in; (void)out_size;
    const float* x      = (const float*)d_in[0];
    const float* y      = (const float*)d_in[1];
    const float* wuu0_w = (const float*)d_in[2];
    const float* wuu0_b = (const float*)d_in[3];
    const float* wyu0_w = (const float*)d_in[4];
    const float* wyu0_b = (const float*)d_in[5];
    const float* wy0    = (const float*)d_in[6];
    const float* wu0_w  = (const float*)d_in[7];
    const float* wu0_b  = (const float*)d_in[8];
    const float* wuu1_w = (const float*)d_in[9];
    const float* wuu1_b = (const float*)d_in[10];
    const float* wzu1_w = (const float*)d_in[11];
    const float* wzu1_b = (const float*)d_in[12];
    const float* wz1    = (const float*)d_in[13];
    const float* wyu1_w = (const float*)d_in[14];
    const float* wyu1_b = (const float*)d_in[15];
    const float* wy1    = (const float*)d_in[16];
    const float* wu1_w  = (const float*)d_in[17];
    const float* wu1_b  = (const float*)d_in[18];
    const float* wzu2_w = (const float*)d_in[19];
    const float* wzu2_b = (const float*)d_in[20];
    const float* wz2    = (const float*)d_in[21];
    const float* wyu2_w = (const float*)d_in[22];
    const float* wyu2_b = (const float*)d_in[23];
    const float* wy2    = (const float*)d_in[24];
    // d_in[25] (wu2_w), d_in[26] (wu2_b) do not affect the gradient / output.

    size_t smem = sizeof(Smem);
    cudaFuncSetAttribute(pblnn_kernel, cudaFuncAttributeMaxDynamicSharedMemorySize, (int)smem);

    pblnn_pre_kernel<<<PCTA, 512>>>(
        x,
        wuu0_w, wuu0_b, wyu0_w, wyu0_b, wu0_w, wu0_b,
        wuu1_w, wuu1_b, wzu1_w, wzu1_b, wyu1_w, wyu1_b, wu1_w, wu1_b,
        wzu2_w, wzu2_b, wz2, wyu2_w, wyu2_b, wy2);
    pblnn_kernel<<<NCTA, NTHREADS, smem>>>(y, wy0, wz1, wy1, (float*)d_out);
}

// round 13
// speedup vs baseline: 1.9760x; 1.1416x over previous
#include <cuda_runtime.h>
#include <math.h>

#define H        128
#define B        256
#define WST      132      // fp32 stride: 132 % 32 == 4 -> conflict-free row+col access
#define SP       260      // packed float2 matrix stride (260 % 32 == 4)
#define PW       (2 * H + 8)
#define NCTA     128
#define NTHREADS 512
#define MAXIT    500
#define TOLF     1e-3f

// per-(iteration, CTA) residual slots; -1 = not posted, >=0 = posted value.
__device__ float g_part[65536];          // >= MAXIT*NCTA
// per-sample loop constants: [a0, c0, zur, a1, c1, a2w, vw2]
__device__ float g_c[7][B * H];

__device__ __forceinline__ float softplus_f(float s) {
    float e = __expf(s);
    float z = __logf(1.f + e);
    return (s > 15.f) ? s : z;
}

// ============================ precompute kernel ============================
// 128 CTAs x 2 samples. Each matrix staged coalesced into smem (double
// buffered against the previous matrix's smem matvec), then the matvec runs
// with the main kernel's conflict-free quarter-split pattern.

struct __align__(16) PSmem {
    float WB0[H * WST];
    float WB1[H * WST];
    float xv[2][H];
    float u0[2][H];
    float u1[2][H];
    float P[4][PW];
    float zu2[2];
};

__device__ __forceinline__ void stage(float* dst, const float* __restrict__ w, int tid) {
#pragma unroll
    for (int i = 0; i < 8; i++) {
        int e = tid + i * 512;
        int r = e >> 5, c4 = (e & 31) * 4;
        *(float4*)&dst[r * WST + c4] = __ldg((const float4*)&w[r * H + c4]);
    }
}

// quarter matvec: smem weights row h seg [k0,k0+32) . two sample vectors
__device__ __forceinline__ void mvq(const float* Wb, const float* v0, const float* v1,
                                    float* Pq, int h, int k0) {
    const float4* W  = (const float4*)&Wb[h * WST + k0];
    const float4* V0 = (const float4*)&v0[k0];
    const float4* V1 = (const float4*)&v1[k0];
    float m0a = 0.f, m0b = 0.f, m1a = 0.f, m1b = 0.f;
#pragma unroll
    for (int c = 0; c < 8; c += 2) {
        float4 w = W[c], a = V0[c], b = V1[c];
        m0a += w.x * a.x + w.y * a.y + w.z * a.z + w.w * a.w;
        m1a += w.x * b.x + w.y * b.y + w.z * b.z + w.w * b.w;
        float4 w2 = W[c + 1], a2 = V0[c + 1], b2 = V1[c + 1];
        m0b += w2.x * a2.x + w2.y * a2.y + w2.z * a2.z + w2.w * a2.w;
        m1b += w2.x * b2.x + w2.y * b2.y + w2.z * b2.z + w2.w * b2.w;
    }
    *(float2*)&Pq[2 * h] = make_float2(m0a + m0b, m1a + m1b);
}

__global__ __launch_bounds__(512, 1)
void pblnn_pre_kernel(
    const float* __restrict__ x,
    const float* __restrict__ wuu0_w, const float* __restrict__ wuu0_b,
    const float* __restrict__ wyu0_w, const float* __restrict__ wyu0_b,
    const float* __restrict__ wu0_w,  const float* __restrict__ wu0_b,
    const float* __restrict__ wuu1_w, const float* __restrict__ wuu1_b,
    const float* __restrict__ wzu1_w, const float* __restrict__ wzu1_b,
    const float* __restrict__ wyu1_w, const float* __restrict__ wyu1_b,
    const float* __restrict__ wu1_w,  const float* __restrict__ wu1_b,
    const float* __restrict__ wzu2_w, const float* __restrict__ wzu2_b,
    const float* __restrict__ wz2,
    const float* __restrict__ wyu2_w, const float* __restrict__ wyu2_b,
    const float* __restrict__ wy2)
{
    extern __shared__ char psm_raw[];
    PSmem& S = *reinterpret_cast<PSmem*>(psm_raw);

    const int tid = threadIdx.x;
    const int l   = tid & 31;
    const int wr  = tid >> 5;
    const int h   = tid & 127;
    const int q   = tid >> 7;
    const int k0  = q * 32;
    const bool act = (q < 2);
    const int s   = q & 1;
    const int ix  = 2 * h + s;
    const int samp0 = blockIdx.x * 2;
    const int gi  = (samp0 + s) * H + h;

    g_part[blockIdx.x * 512 + tid] = -1.f;   // residual-slot init (128*512 = 65536)

    if (tid < 256) S.xv[tid >> 7][tid & 127] = x[samp0 * H + tid];
    stage(S.WB0, wuu0_w, tid);
    __syncthreads();

    // step 0: mv wuu0@x -> u0 ; stage wyu0
    stage(S.WB1, wyu0_w, tid);
    mvq(S.WB0, S.xv[0], S.xv[1], S.P[q], h, k0);
    __syncthreads();
    if (act) {
        float t = S.P[0][ix] + S.P[1][ix] + S.P[2][ix] + S.P[3][ix];
        S.u0[s][h] = softplus_f(t + wuu0_b[h]);
    }
    __syncthreads();

    // step 1: mv wyu0@x -> a0 ; stage wu0
    stage(S.WB0, wu0_w, tid);
    mvq(S.WB1, S.xv[0], S.xv[1], S.P[q], h, k0);
    __syncthreads();
    if (act)
        g_c[0][gi] = S.P[0][ix] + S.P[1][ix] + S.P[2][ix] + S.P[3][ix] + wyu0_b[h];
    __syncthreads();

    // step 2: mv wu0@x -> c0 ; stage wuu1
    stage(S.WB1, wuu1_w, tid);
    mvq(S.WB0, S.xv[0], S.xv[1], S.P[q], h, k0);
    __syncthreads();
    if (act)
        g_c[1][gi] = S.P[0][ix] + S.P[1][ix] + S.P[2][ix] + S.P[3][ix] + wu0_b[h];
    __syncthreads();

    // step 3: mv wuu1@u0 -> u1 ; stage wzu1
    stage(S.WB0, wzu1_w, tid);
    mvq(S.WB1, S.u0[0], S.u0[1], S.P[q], h, k0);
    __syncthreads();
    if (act) {
        float t = S.P[0][ix] + S.P[1][ix] + S.P[2][ix] + S.P[3][ix];
        S.u1[s][h] = softplus_f(t + wuu1_b[h]);
    }
    __syncthreads();

    // step 4: mv wzu1@u0 -> zur ; stage wyu1
    stage(S.WB1, wyu1_w, tid);
    mvq(S.WB0, S.u0[0], S.u0[1], S.P[q], h, k0);
    __syncthreads();
    if (act) {
        float t = S.P[0][ix] + S.P[1][ix] + S.P[2][ix] + S.P[3][ix];
        g_c[2][gi] = softplus_f(t + wzu1_b[h]);
    }
    __syncthreads();

    // step 5: mv wyu1@u0 -> a1 ; stage wu1
    stage(S.WB0, wu1_w, tid);
    mvq(S.WB1, S.u0[0], S.u0[1], S.P[q], h, k0);
    __syncthreads();
    if (act)
        g_c[3][gi] = S.P[0][ix] + S.P[1][ix] + S.P[2][ix] + S.P[3][ix] + wyu1_b[h];
    __syncthreads();

    // step 6: mv wu1@u0 -> c1 ; stage wyu2
    stage(S.WB1, wyu2_w, tid);
    mvq(S.WB0, S.u0[0], S.u0[1], S.P[q], h, k0);
    __syncthreads();
    if (act)
        g_c[4][gi] = S.P[0][ix] + S.P[1][ix] + S.P[2][ix] + S.P[3][ix] + wu1_b[h];
    __syncthreads();

    // step 7: mv wyu2@u1 -> a2w ; warps 14/15 compute zu2[s]
    mvq(S.WB1, S.u1[0], S.u1[1], S.P[q], h, k0);
    if (wr >= 14) {
        int ss = wr - 14;
        float4 wv = __ldg((const float4*)&wzu2_w[4 * l]);
        float4 uv = *(const float4*)&S.u1[ss][4 * l];
        float sv = wv.x*uv.x + wv.y*uv.y + wv.z*uv.z + wv.w*uv.w;
#pragma unroll
        for (int o = 16; o; o >>= 1)
            sv += __shfl_xor_sync(0xffffffffu, sv, o);
        if (l == 0) S.zu2[ss] = softplus_f(sv + wzu2_b[0]);
    }
    __syncthreads();
    if (act) {
        float t = S.P[0][ix] + S.P[1][ix] + S.P[2][ix] + S.P[3][ix];
        g_c[5][gi] = (t + wyu2_b[h]) * wy2[h];
        g_c[6][gi] = S.zu2[s] * fmaxf(wz2[h], 0.f);
    }
}

// ============================== main kernel ===============================

struct __align__(16) Smem {
    float Wy0[H * WST];       // fp32 rows (M1) + scalar cols (D)
    float WP[H * SP];         // interleaved (W1p, Wy1): rows (M2) + col float2 (C)
    float yv0[2][H];
    float yv1[2][H];
    float zz [2][H];
    float v2 [2][H];
    float v1 [2][H];
    float P1[4][PW];          // packed partials: [q][2h+s]
    float P2[4][PW];
    float red[8];
    int   flag;
};

__device__ __forceinline__ void spsig(float s, float& z, float& sg) {
    float e = __expf(s);
    float zz_ = __logf(1.f + e);
    float sgg = e / (1.f + e);
    if (s > 15.f) { zz_ = s; sgg = 1.f; }
    z = zz_; sg = sgg;
}

__global__ __launch_bounds__(NTHREADS, 1)
void pblnn_kernel(
    const float* __restrict__ y,
    const float* __restrict__ wy0,
    const float* __restrict__ wz1,
    const float* __restrict__ wy1,
    float* __restrict__ out)
{
    extern __shared__ char smem_raw[];
    Smem& S = *reinterpret_cast<Smem*>(smem_raw);

    const int tid  = threadIdx.x;
    const int lane = tid & 31;
    const int wrp  = tid >> 5;
    const int h    = tid & (H - 1);
    const int q    = tid >> 7;          // quarter 0..3
    const int k0   = q * 32;
    const bool act = (q < 2);           // elementwise lanes; s = q
    const int s    = q & 1;
    const int samp = blockIdx.x * 2;

    // ---- stage loop weights into smem ----
    for (int e = tid; e < H * H / 4; e += NTHREADS) {
        int r = e >> 5, c4 = (e & 31) * 4;
        *(float4*)&S.Wy0[r * WST + c4] = __ldg((const float4*)&wy0[r * H + c4]);
        float4 w1 = __ldg((const float4*)&wz1[r * H + c4]);
        w1.x = fmaxf(w1.x, 0.f); w1.y = fmaxf(w1.y, 0.f);
        w1.z = fmaxf(w1.z, 0.f); w1.w = fmaxf(w1.w, 0.f);
        float4 wy = __ldg((const float4*)&wy1[r * H + c4]);
        float4 lo = make_float4(w1.x, wy.x, w1.y, wy.y);
        float4 hi = make_float4(w1.z, wy.z, w1.w, wy.w);
        *(float4*)&S.WP[r * SP + 2 * c4]     = lo;
        *(float4*)&S.WP[r * SP + 2 * c4 + 4] = hi;
    }

    // ---- load per-sample constants from precompute scratch ----
    float a0r = 0.f, c0r = 0.f, zur = 0.f, a1r = 0.f, c1r = 0.f;
    float a2w = 0.f, vw2 = 0.f, yr = 0.f;
    float y1r = 1.f, yhist = 1.f, zs1r = 0.f, gAr = 0.f;
    if (act) {
        int gi = (samp + s) * H + h;
        a0r = g_c[0][gi];  c0r = g_c[1][gi];  zur = g_c[2][gi];
        a1r = g_c[3][gi];  c1r = g_c[4][gi];
        a2w = g_c[5][gi];  vw2 = g_c[6][gi];
        yr  = y[gi];
        S.yv0[s][h] = a0r;      // y1 = 1
        S.yv1[s][h] = a1r;
    }
    __syncthreads();            // weights + yv ready for iter 0

    // ---- fixed-point iterations: lag-2, atomic-free convergence pipeline ----
    int broke = 0;
    for (int it = 0; it < MAXIT; ++it) {
        // post residual of it-1: one plain volatile store, value doubles as flag
        if (tid == 416 && it > 0) {
            float n0 = sqrtf(S.red[0] + S.red[1] + S.red[2] + S.red[3]);
            float n1 = sqrtf(S.red[4] + S.red[5] + S.red[6] + S.red[7]);
            *((volatile float*)&g_part[(it - 1) * NCTA + blockIdx.x]) = n0 + n1;
        }
        // checker warp: cooperative poll + sum of lag-2 slots (overlaps M1)
        if (wrp == 12) {
            int f = 0;
            if (it >= 2) {
                volatile const float* gp = &g_part[(it - 2) * NCTA];
                float sum;
                for (;;) {
                    float v0 = gp[lane], v1 = gp[lane + 32];
                    float v2 = gp[lane + 64], v3 = gp[lane + 96];
                    bool ok = (v0 >= 0.f) & (v1 >= 0.f) & (v2 >= 0.f) & (v3 >= 0.f);
                    if (__all_sync(0xffffffffu, ok)) { sum = v0 + v1 + v2 + v3; break; }
                }
#pragma unroll
                for (int o = 16; o; o >>= 1)
                    sum += __shfl_xor_sync(0xffffffffu, sum, o);
                if (sum * (1.f / 256.f) < TOLF) f = 1;
            }
            if (lane == 0) S.flag = f;
        }

        // M1: s1 partial = Wy0[h][k0..k0+32) . yv0
        {
            const float4* W  = (const float4*)&S.Wy0[h * WST + k0];
            const float4* V0 = (const float4*)&S.yv0[0][k0];
            const float4* V1 = (const float4*)&S.yv0[1][k0];
            float m0a = 0.f, m0b = 0.f, m1a = 0.f, m1b = 0.f;
#pragma unroll
            for (int c = 0; c < 8; c += 2) {
                float4 w = W[c], a = V0[c], b = V1[c];
                m0a += w.x * a.x + w.y * a.y + w.z * a.z + w.w * a.w;
                m1a += w.x * b.x + w.y * b.y + w.z * b.z + w.w * b.w;
                float4 w2 = W[c + 1], a2 = V0[c + 1], b2 = V1[c + 1];
                m0b += w2.x * a2.x + w2.y * a2.y + w2.z * a2.z + w2.w * a2.w;
                m1b += w2.x * b2.x + w2.y * b2.y + w2.z * b2.z + w2.w * b2.w;
            }
            *(float2*)&S.P1[q][2 * h] = make_float2(m0a + m0b, m1a + m1b);
        }
        __syncthreads();                                   // #2

        // flag = conv(it-2), stable after #2; break BEFORE this iteration's update.
        if (S.flag) { broke = 1; break; }

        if (act) {
            int ix = 2 * h + s;
            float s1 = S.P1[0][ix] + S.P1[1][ix] + S.P1[2][ix] + S.P1[3][ix] + c0r;
            float z1, sg1;
            spsig(s1, z1, sg1);
            zs1r = sg1 * zur;
            S.zz[s][h] = z1 * zur;
        }
        __syncthreads();                                   // #3

        // M2: s2 partial = W1p@zz + Wy1@yv1 via packed WP rows
        {
            const float4* WA = (const float4*)&S.WP[h * SP + 2 * k0];
            const float4* Z0 = (const float4*)&S.zz[0][k0];
            const float4* Z1 = (const float4*)&S.zz[1][k0];
            const float4* Y0 = (const float4*)&S.yv1[0][k0];
            const float4* Y1 = (const float4*)&S.yv1[1][k0];
            float mA0 = 0.f, mA1 = 0.f, mB0 = 0.f, mB1 = 0.f;
#pragma unroll
            for (int c = 0; c < 8; c++) {
                float4 wlo = WA[2 * c];
                float4 whi = WA[2 * c + 1];
                float4 z0 = Z0[c], z1v = Z1[c], u0v = Y0[c], u1v = Y1[c];
                mA0 += wlo.x * z0.x + wlo.z * z0.y + whi.x * z0.z + whi.z * z0.w;
                mB0 += wlo.y * u0v.x + wlo.w * u0v.y + whi.y * u0v.z + whi.w * u0v.w;
                mA1 += wlo.x * z1v.x + wlo.z * z1v.y + whi.x * z1v.z + whi.z * z1v.w;
                mB1 += wlo.y * u1v.x + wlo.w * u1v.y + whi.y * u1v.z + whi.w * u1v.w;
            }
            *(float2*)&S.P1[q][2 * h] = make_float2(mA0 + mB0, mA1 + mB1);
        }
        __syncthreads();                                   // #4

        if (act) {
            int ix = 2 * h + s;
            float s2 = S.P1[0][ix] + S.P1[1][ix] + S.P1[2][ix] + S.P1[3][ix] + c1r;
            float sg2 = 1.f / (1.f + __expf(-s2));
            S.v2[s][h] = vw2 * sg2;
        }
        __syncthreads();                                   // #5

        // C: tv partial (W1p cols) + gA partial (Wy1 cols) via packed WP col float2
        {
            float tA0 = 0.f, tA1 = 0.f, gA0 = 0.f, gA1 = 0.f;
#pragma unroll
            for (int c = 0; c < 8; c++) {
                int kp = k0 + 4 * c;
                float4 a = *(const float4*)&S.v2[0][kp];
                float4 b = *(const float4*)&S.v2[1][kp];
#define STC(r, av, bv) { \
                float2 wc = *(const float2*)&S.WP[(kp + r) * SP + 2 * h]; \
                tA0 += (av) * wc.x;  tA1 += (bv) * wc.x; \
                gA0 += (av) * wc.y;  gA1 += (bv) * wc.y; }
                STC(0, a.x, b.x) STC(1, a.y, b.y) STC(2, a.z, b.z) STC(3, a.w, b.w)
#undef STC
            }
            *(float2*)&S.P1[q][2 * h] = make_float2(tA0, tA1);
            *(float2*)&S.P2[q][2 * h] = make_float2(gA0, gA1);
        }
        __syncthreads();                                   // #6

        if (act) {
            int ix = 2 * h + s;
            float tv = S.P1[0][ix] + S.P1[1][ix] + S.P1[2][ix] + S.P1[3][ix];
            gAr      = S.P2[0][ix] + S.P2[1][ix] + S.P2[2][ix] + S.P2[3][ix];
            S.v1[s][h] = tv * zs1r;
        }
        __syncthreads();                                   // #7

        // D: gB partial (Wy0 cols, scalar)
        {
            float g0 = 0.f, g1 = 0.f;
#pragma unroll
            for (int c = 0; c < 8; c++) {
                int kp = k0 + 4 * c;
                float4 a = *(const float4*)&S.v1[0][kp];
                float4 b = *(const float4*)&S.v1[1][kp];
#define STD(r, av, bv) { \
                float w = S.Wy0[(kp + r) * WST + h]; \
                g0 += (av) * w;  g1 += (bv) * w; }
                STD(0, a.x, b.x) STD(1, a.y, b.y) STD(2, a.z, b.z) STD(3, a.w, b.w)
#undef STD
            }
            *(float2*)&S.P1[q][2 * h] = make_float2(g0, g1);
        }
        __syncthreads();                                   // #8

        float rres = 0.f;
        if (act) {
            int ix = 2 * h + s;
            float gB = S.P1[0][ix] + S.P1[1][ix] + S.P1[2][ix] + S.P1[3][ix];
            float g = a1r * gAr + a0r * gB + a2w + 0.5f * y1r;
            rres = yr - g;
            float qq = rres * rres;
#pragma unroll
            for (int o = 16; o; o >>= 1)
                qq += __shfl_xor_sync(0xffffffffu, qq, o);
            if ((h & 31) == 0) S.red[tid >> 5] = qq;   // warps 0..7
        }

        if (act) {
            yhist = y1r;                       // y1_after(it-1)
            y1r += (4.f / (float)(it + 1)) * rres;
            S.yv0[s][h] = y1r * a0r;
            S.yv1[s][h] = y1r * a1r;
        }
        __syncthreads();     // #E: red/yv ready; flag not yet overwritten
    }
    if (broke && act) y1r = yhist;   // exact revert to y1_after(break_it - 2)

    // ---- output: mean over dims of (y1 + y) per sample ----
    float o = act ? (y1r + yr) : 0.f;
    if (act) {
#pragma unroll
        for (int off = 16; off; off >>= 1)
            o += __shfl_xor_sync(0xffffffffu, o, off);
        if ((h & 31) == 0) S.red[tid >> 5] = o;
    }
    __syncthreads();
    if (tid == 0) {
        out[samp]     = (S.red[0] + S.red[1] + S.red[2] + S.red[3]) * (1.f / 128.f);
        out[samp + 1] = (S.red[4] + S.red[5] + S.red[6] + S.red[7]) * (1.f / 128.f);
    }
}

extern "C" void kernel_launch(void* const* d_in, const int* in_sizes, int n_in,
                              void* d_out, int out_size) {
    (void)in_sizes; (void)n_in; (void)out_size;
    const float* x      = (const float*)d_in[0];
    const float* y      = (const float*)d_in[1];
    const float* wuu0_w = (const float*)d_in[2];
    const float* wuu0_b = (const float*)d_in[3];
    const float* wyu0_w = (const float*)d_in[4];
    const float* wyu0_b = (const float*)d_in[5];
    const float* wy0    = (const float*)d_in[6];
    const float* wu0_w  = (const float*)d_in[7];
    const float* wu0_b  = (const float*)d_in[8];
    const float* wuu1_w = (const float*)d_in[9];
    const float* wuu1_b = (const float*)d_in[10];
    const float* wzu1_w = (const float*)d_in[11];
    const float* wzu1_b = (const float*)d_in[12];
    const float* wz1    = (const float*)d_in[13];
    const float* wyu1_w = (const float*)d_in[14];
    const float* wyu1_b = (const float*)d_in[15];
    const float* wy1    = (const float*)d_in[16];
    const float* wu1_w  = (const float*)d_in[17];
    const float* wu1_b  = (const float*)d_in[18];
    const float* wzu2_w = (const float*)d_in[19];
    const float* wzu2_b = (const float*)d_in[20];
    const float* wz2    = (const float*)d_in[21];
    const float* wyu2_w = (const float*)d_in[22];
    const float* wyu2_b = (const float*)d_in[23];
    const float* wy2    = (const float*)d_in[24];
    // d_in[25] (wu2_w), d_in[26] (wu2_b) do not affect the gradient / output.

    size_t psmem = sizeof(PSmem);
    size_t smem  = sizeof(Smem);
    cudaFuncSetAttribute(pblnn_pre_kernel, cudaFuncAttributeMaxDynamicSharedMemorySize, (int)psmem);
    cudaFuncSetAttribute(pblnn_kernel, cudaFuncAttributeMaxDynamicSharedMemorySize, (int)smem);

    pblnn_pre_kernel<<<NCTA, 512, psmem>>>(
        x,
        wuu0_w, wuu0_b, wyu0_w, wyu0_b, wu0_w, wu0_b,
        wuu1_w, wuu1_b, wzu1_w, wzu1_b, wyu1_w, wyu1_b, wu1_w, wu1_b,
        wzu2_w, wzu2_b, wz2, wyu2_w, wyu2_b, wy2);
    pblnn_kernel<<<NCTA, NTHREADS, smem>>>(y, wy0, wz1, wy1, (float*)d_out);
}